// round 11
// baseline (speedup 1.0000x reference)
#include <cuda_runtime.h>
#include <cuda_fp16.h>
#include <cstdint>
#include <cstddef>

// ---------------- problem dims ----------------
#define nB 8
#define nS 2048
#define nD 1024
#define nH 4096
#define nE 8
constexpr int TMM = 128, TNN = 256;               // CTA tile
constexpr int NSTG = 4;                           // pipeline stages
// stage: A 128 rows x 128B K (16KB) + B 256 n-rows x 128B K (32KB)
constexpr int STAGE_TC = 128*128 + 4*8192;        // 49152
constexpr int SMEM_GEMM = 1024 + NSTG*STAGE_TC;   // 197632

#define SWZ(o) ((o) ^ (((o) >> 3) & 0x70u))

// Arch-specific gate: tcgen05 exists only in sm_103a/sm_100a cubins.
#if defined(__CUDA_ARCH__) && (defined(__CUDA_ARCH_FEAT_SM103_ALL) || \
    defined(__CUDA_ARCH_FEAT_SM100_ALL) || \
    (defined(__CUDA_ARCH_SPECIFIC__) && (__CUDA_ARCH_SPECIFIC__ >= 1000)))
#define HAS_TCGEN05 1
#else
#define HAS_TCGEN05 0
#endif

// idesc kind::f16: F32 accum (bit4), N=64 -> (N/8)<<17, M=128 -> (M/16)<<24. K-major A and B.
constexpr uint32_t IDESC = (1u<<4) | ((64u/8)<<17) | ((128u/16)<<24);
// K-major SW128 smem descriptor: LBO=1, SBO=64
static __device__ constexpr uint64_t DESC_K  =
    (uint64_t(2)<<61) | (uint64_t(1)<<46) | (uint64_t(64)<<32) | (uint64_t(1)<<16);

// ---------------- device scratch ----------------
__device__ __align__(256) __half g_xh [nB*nS*nD];
__device__ __align__(256) __half g_W1t[(size_t)nE*nH*nD];   // W1^T: [E][H][D] (K=D contiguous)
__device__ __align__(256) __half g_W2t[(size_t)nE*nD*nH];   // W2^T: [E][D][H] (K=H contiguous)
__device__ __align__(256) __half g_h  [(size_t)nB*nS*2*nH];
__device__ float g_rout[nB*nD];
__device__ float g_tw  [nB*2];
__device__ int   g_tidx[nB*2];
__device__ int   g_used[nE];

// ---------------- portable PTX helpers ----------------
__device__ __forceinline__ uint32_t smem_u32(const void* p){
    uint32_t a;
    asm("{ .reg .u64 t; cvta.to.shared.u64 t, %1; cvt.u32.u64 %0, t; }" : "=r"(a) : "l"(p));
    return a;
}
__device__ __forceinline__ void cp_async16(uint32_t s, const void* g){
    asm volatile("cp.async.cg.shared.global [%0], [%1], 16;" :: "r"(s), "l"(g));
}
__device__ __forceinline__ void cp_commit(){ asm volatile("cp.async.commit_group;" ::: "memory"); }

#define LDSM4(r, a) \
    asm volatile("ldmatrix.sync.aligned.m8n8.x4.shared.b16 {%0,%1,%2,%3}, [%4];" \
        : "=r"((r)[0]), "=r"((r)[1]), "=r"((r)[2]), "=r"((r)[3]) : "r"(a))
#define MMA16816(d, a, b0, b1) \
    asm volatile("mma.sync.aligned.m16n8k16.row.col.f32.f16.f16.f32 " \
        "{%0,%1,%2,%3}, {%4,%5,%6,%7}, {%8,%9}, {%0,%1,%2,%3};" \
        : "+f"((d)[0]), "+f"((d)[1]), "+f"((d)[2]), "+f"((d)[3]) \
        : "r"((a)[0]), "r"((a)[1]), "r"((a)[2]), "r"((a)[3]), "r"(b0), "r"(b1))

#if HAS_TCGEN05
__device__ __forceinline__ uint32_t elect_one(){
    uint32_t p;
    asm volatile("{ .reg .pred p; elect.sync _|p, 0xFFFFFFFF; selp.b32 %0, 1, 0, p; }" : "=r"(p));
    return p;
}
#define MBAR_INIT(a, c) \
    asm volatile("mbarrier.init.shared.b64 [%0], %1;" :: "r"(a), "r"(c) : "memory")

// Bounded parity wait: a broken pipeline produces a FAST wrong answer
// (diagnosable rel_err) instead of a 120 s timeout.
__device__ __forceinline__ bool mbar_wait_bounded(uint32_t m, uint32_t par){
    for (int i = 0; i < (1 << 17); i++){
        uint32_t d;
        asm volatile("{\n\t.reg .pred p;\n\t"
            "mbarrier.try_wait.parity.acquire.cta.shared::cta.b64 p, [%1], %2;\n\t"
            "selp.b32 %0, 1, 0, p;\n\t}" : "=r"(d) : "r"(m), "r"(par) : "memory");
        if (d) return true;
    }
    return false;
}

#define TC_ALLOC(sa, n) \
    asm volatile("tcgen05.alloc.cta_group::1.sync.aligned.shared::cta.b32 [%0], %1;" \
        :: "r"(sa), "r"(n) : "memory")
#define TC_DEALLOC(t, n) \
    asm volatile("tcgen05.dealloc.cta_group::1.sync.aligned.b32 %0, %1;" :: "r"(t), "r"(n))
#define TC_RELINQ() \
    asm volatile("tcgen05.relinquish_alloc_permit.cta_group::1.sync.aligned;")
#define TC_COMMIT(a) \
    asm volatile("tcgen05.commit.cta_group::1.mbarrier::arrive::one.shared::cluster.b64 [%0];" \
        :: "r"(a) : "memory")
#define TC_WAIT_LD()  asm volatile("tcgen05.wait::ld.sync.aligned;" ::: "memory")
#define TC_FENCE_BEFORE() asm volatile("tcgen05.fence::before_thread_sync;" ::: "memory")
#define TC_FENCE_AFTER()  asm volatile("tcgen05.fence::after_thread_sync;" ::: "memory")
#define TC_LD_X32(r, ta) \
    asm volatile( \
        "tcgen05.ld.sync.aligned.32x32b.x32.b32 " \
        "{%0, %1, %2, %3, %4, %5, %6, %7, " \
        " %8, %9, %10, %11, %12, %13, %14, %15, " \
        " %16, %17, %18, %19, %20, %21, %22, %23, " \
        " %24, %25, %26, %27, %28, %29, %30, %31}, [%32];" \
        : "=r"((r)[0]),  "=r"((r)[1]),  "=r"((r)[2]),  "=r"((r)[3]), \
          "=r"((r)[4]),  "=r"((r)[5]),  "=r"((r)[6]),  "=r"((r)[7]), \
          "=r"((r)[8]),  "=r"((r)[9]),  "=r"((r)[10]), "=r"((r)[11]), \
          "=r"((r)[12]), "=r"((r)[13]), "=r"((r)[14]), "=r"((r)[15]), \
          "=r"((r)[16]), "=r"((r)[17]), "=r"((r)[18]), "=r"((r)[19]), \
          "=r"((r)[20]), "=r"((r)[21]), "=r"((r)[22]), "=r"((r)[23]), \
          "=r"((r)[24]), "=r"((r)[25]), "=r"((r)[26]), "=r"((r)[27]), \
          "=r"((r)[28]), "=r"((r)[29]), "=r"((r)[30]), "=r"((r)[31]) \
        : "r"(ta))
__device__ __forceinline__ void mma_f16_ss(uint32_t d, uint64_t ad, uint64_t bd,
                                           uint32_t idesc, uint32_t en){
    asm volatile(
        "{\n\t.reg .pred p;\n\tsetp.ne.u32 p, %5, 0;\n\t"
        "tcgen05.mma.cta_group::1.kind::f16 [%0], %1, %2, %3, {%4, %4, %4, %4}, p;\n\t}"
        :: "r"(d), "l"(ad), "l"(bd), "r"(idesc), "r"(0u), "r"(en) : "memory");
}
#endif

// ---------------- small kernels ----------------
__global__ void k_zero(){
    int t = threadIdx.x;
    for (int i = t; i < nB*nD; i += 256) g_rout[i] = 0.f;
    if (t < nE) g_used[t] = 0;
}

__global__ void k_convx(const float* __restrict__ x){
    int sc = blockIdx.x, b = blockIdx.y, t = threadIdx.x;
    size_t base = ((size_t)b*nS + (size_t)sc*128) * nD;
    float a0=0.f, a1=0.f, a2=0.f, a3=0.f;
    for (int s = 0; s < 128; s++) {
        float4 v = reinterpret_cast<const float4*>(x + base + (size_t)s*nD)[t];
        a0 += v.x; a1 += v.y; a2 += v.z; a3 += v.w;
        __half2 ha = __floats2half2_rn(v.x, v.y);
        __half2 hb = __floats2half2_rn(v.z, v.w);
        uint2 u = make_uint2(*reinterpret_cast<uint32_t*>(&ha),
                             *reinterpret_cast<uint32_t*>(&hb));
        *reinterpret_cast<uint2*>(&g_xh[base + (size_t)s*nD + t*4]) = u;
    }
    const float inv = 1.f / (float)nS;
    atomicAdd(&g_rout[b*nD + t*4 + 0], a0*inv);
    atomicAdd(&g_rout[b*nD + t*4 + 1], a1*inv);
    atomicAdd(&g_rout[b*nD + t*4 + 2], a2*inv);
    atomicAdd(&g_rout[b*nD + t*4 + 3], a3*inv);
}

__global__ void k_gate(const float* __restrict__ Wg1, const float* __restrict__ bg1,
                       const float* __restrict__ Wg2, const float* __restrict__ bg2,
                       float* __restrict__ out, long out_size){
    __shared__ float rs[nD], gs[nD], lg[nE];
    int b = blockIdx.x, t = threadIdx.x;
    for (int i = t; i < nD; i += 256) rs[i] = g_rout[b*nD + i];
    __syncthreads();
    for (int j = t; j < nD; j += 256) {
        float a = 0.f;
        for (int d = 0; d < nD; d++) a += rs[d] * Wg1[(size_t)d*nD + j];
        a += bg1[j];
        gs[j] = a / (1.f + __expf(-a));
    }
    __syncthreads();
    if (t < nE) {
        float a = 0.f;
        for (int d = 0; d < nD; d++) a += gs[d] * Wg2[d*nE + t];
        lg[t] = a + bg2[t];
    }
    __syncthreads();
    if (t == 0) {
        int i0 = 0;
        for (int e = 1; e < nE; e++) if (lg[e] > lg[i0]) i0 = e;
        int i1 = -1;
        for (int e = 0; e < nE; e++) { if (e == i0) continue; if (i1 < 0 || lg[e] > lg[i1]) i1 = e; }
        float ex = __expf(lg[i1] - lg[i0]);
        float w0 = 1.f / (1.f + ex), w1 = ex / (1.f + ex);
        g_tw[b*2] = w0;  g_tw[b*2+1] = w1;
        g_tidx[b*2] = i0; g_tidx[b*2+1] = i1;
        g_used[i0] = 1;   g_used[i1] = 1;
        const long BSD = (long)nB*nS*nD;
        if (out_size >= BSD + 32) {
            out[BSD + b*2 + 0] = w0;  out[BSD + b*2 + 1] = w1;
            out[BSD + 16 + b*2 + 0] = (float)i0;
            out[BSD + 16 + b*2 + 1] = (float)i1;
        }
    }
}

// Transpose-convert W1 [E][D][H] fp32 -> g_W1t [E][H][D] fp16 (K-major for GEMM1 B).
__global__ void k_convw1(const float* __restrict__ W){
    int e = blockIdx.z;
    if (!g_used[e]) return;
    __shared__ float s[32][33];
    int h0 = blockIdx.x * 32, d0 = blockIdx.y * 32;
    int tx = threadIdx.x & 31, ty = threadIdx.x >> 5;        // 32 x 8
    const float* Wp = W + (size_t)e*nD*nH;
    #pragma unroll
    for (int i = 0; i < 4; i++)
        s[ty + i*8][tx] = Wp[(size_t)(d0 + ty + i*8)*nH + h0 + tx];
    __syncthreads();
    __half* Wt = g_W1t + (size_t)e*nH*nD;
    #pragma unroll
    for (int i = 0; i < 4; i++)
        Wt[(size_t)(h0 + ty + i*8)*nD + d0 + tx] = __float2half_rn(s[tx][ty + i*8]);
}
// Transpose-convert W2 [E][H][D] fp32 -> g_W2t [E][D][H] fp16 (K-major for GEMM2 B).
__global__ void k_convw2(const float* __restrict__ W){
    int e = blockIdx.z;
    if (!g_used[e]) return;
    __shared__ float s[32][33];
    int d0 = blockIdx.x * 32, h0 = blockIdx.y * 32;
    int tx = threadIdx.x & 31, ty = threadIdx.x >> 5;
    const float* Wp = W + (size_t)e*nH*nD;
    #pragma unroll
    for (int i = 0; i < 4; i++)
        s[ty + i*8][tx] = Wp[(size_t)(h0 + ty + i*8)*nD + d0 + tx];
    __syncthreads();
    __half* Wt = g_W2t + (size_t)e*nD*nH;
    #pragma unroll
    for (int i = 0; i < 4; i++)
        Wt[(size_t)(d0 + ty + i*8)*nH + h0 + tx] = __float2half_rn(s[tx][ty + i*8]);
}

// ---------------- fused GEMM, CTA tile 128x256, B K-major ----------------
// Grid: x = m-tile (FASTEST — concurrent CTAs share one B slab via L2),
//       y = n-tile, z = (b,kslot) / b.
// mode 1: per (b,kslot):  g_h[b,:,kslot*H..] = silu(x[b] @ W1[e] + b1[e]) * topk_w
// mode 2: per b:          out[b] = g_h[b] @ [W2[e0]; W2[e1]] + (w0*b2[e0] + w1*b2[e1])
__global__ __launch_bounds__(256, 1) __cluster_dims__(1, 1, 1)
void k_moe_gemm(const float* __restrict__ b1, const float* __restrict__ b2,
                float* __restrict__ out, int mode){
    extern __shared__ char smem[];
    uint32_t sbase = smem_u32(smem);
    int t = threadIdx.x, wid = t >> 5, lid = t & 31;

    int m0 = blockIdx.x * TMM;          // m fastest => B-slab reuse across the wave
    int n0 = blockIdx.y * TNN;
    int z  = blockIdx.z;

    const __half* Ap; const __half *B0, *B1;
    int ldA, ldB, KT, bb, kslot = 0, e0, e1 = 0;
    float w0s, w1s = 0.f;
    if (mode == 1) {
        bb = z >> 1; kslot = z & 1;
        e0 = g_tidx[bb*2 + kslot]; w0s = g_tw[bb*2 + kslot];
        Ap = g_xh + (size_t)bb*nS*nD; ldA = nD; KT = nD/64;
        B0 = g_W1t + (size_t)e0*nH*nD; B1 = B0; ldB = nD;
    } else {
        bb = z;
        e0 = g_tidx[bb*2]; e1 = g_tidx[bb*2+1];
        w0s = g_tw[bb*2];  w1s = g_tw[bb*2+1];
        Ap = g_h + (size_t)bb*nS*2*nH; ldA = 2*nH; KT = 2*nH/64;
        B0 = g_W2t + (size_t)e0*nD*nH; B1 = g_W2t + (size_t)e1*nD*nH; ldB = nH;
    }
    const char* Abase = (const char*)Ap + (size_t)m0 * (size_t)ldA * 2;
    size_t ldAb = (size_t)ldA * 2, ldBb = (size_t)ldB * 2;

    // Shared loader: A [128 m-rows x 128B k], B 4 subtiles [64 n-rows x 128B k], SW128.
    auto load_stage = [&](int kt, uint32_t tiles, int stage_bytes){
        uint32_t sA = tiles + (uint32_t)(kt & (NSTG-1)) * stage_bytes;
        uint32_t sB = sA + 128*128;
        const char* Ak = Abase + (size_t)kt * 128;
        const __half* Bexp = (mode == 2 && kt >= 64) ? B1 : B0;
        int kcol0 = (mode == 2 && kt >= 64) ? (kt - 64) * 64 : kt * 64;
        const char* Bk = (const char*)Bexp + (size_t)n0 * ldBb + (size_t)kcol0 * 2;
        #pragma unroll
        for (int it = 0; it < 12; it++) {
            int g = t + it * 256;
            if (g < 1024) {                      // A: 128 rows x 8 x 16B
                int row = g >> 3, c = g & 7;
                uint32_t off = (uint32_t)(row*128 + c*16);
                cp_async16(sA + SWZ(off), Ak + (size_t)row*ldAb + c*16);
            } else {                             // B: 4 subtiles x 64 n-rows x 8 x 16B
                int gg = g - 1024;
                int j = gg >> 9, r = (gg >> 3) & 63, c = gg & 7;
                uint32_t off = (uint32_t)(r*128 + c*16);
                cp_async16(sB + j*8192 + SWZ(off),
                           Bk + (size_t)(j*64 + r)*ldBb + c*16);
            }
        }
        cp_commit();
    };

#if HAS_TCGEN05
    // ================= tcgen05 path — lag-1 commit waits, 3-deep prefetch =================
    // iter kt: wait stage kt loads; issue MMA kt + commit; wait commit kt-1
    // (complete — it had a full load period); THEN load stage kt+3, whose
    // buffer (kt-1)&3 was read by MMA kt-1, just confirmed done.
    uint32_t mbar  = sbase + 8;
    uint32_t tiles = (sbase + 1024) & ~1023u;

    if (t == 0) MBAR_INIT(mbar, 1);
    if (wid == 0) TC_ALLOC(sbase, 512);
    __syncthreads();
    uint32_t tmem;
    asm volatile("ld.shared.b32 %0, [%1];" : "=r"(tmem) : "r"(sbase));

    load_stage(0, tiles, STAGE_TC);
    load_stage(1, tiles, STAGE_TC);
    load_stage(2, tiles, STAGE_TC);

    bool alive = true;
    for (int kt = 0; kt < KT; kt++) {
        if (kt + 2 < KT)      asm volatile("cp.async.wait_group 2;" ::: "memory");
        else if (kt + 1 < KT) asm volatile("cp.async.wait_group 1;" ::: "memory");
        else                  asm volatile("cp.async.wait_group 0;" ::: "memory");
        __syncthreads();
        if (wid == 0) {
            if (elect_one()) {
                TC_FENCE_AFTER();
                asm volatile("fence.proxy.async.shared::cta;" ::: "memory");
                uint32_t sA = tiles + (uint32_t)(kt & (NSTG-1)) * STAGE_TC;
                uint32_t sB = sA + 128*128;
                uint64_t ad = DESC_K | ((sA >> 4) & 0x3FFF);
                #pragma unroll
                for (int ks = 0; ks < 4; ks++) {
                    uint32_t en = (kt > 0 || ks > 0) ? 1u : 0u;
                    #pragma unroll
                    for (int j = 0; j < 4; j++) {
                        uint64_t bd = DESC_K | (((sB + j*8192) >> 4) & 0x3FFF);
                        mma_f16_ss(tmem + 64*j, ad + ks*2, bd + ks*2, IDESC, en);
                    }
                }
                TC_COMMIT(mbar);
            }
        }
        if (kt >= 1 && alive) alive = mbar_wait_bounded(mbar, (uint32_t)((kt-1) & 1));
        if (kt + 3 < KT) load_stage(kt + 3, tiles, STAGE_TC);
    }
    if (alive) alive = mbar_wait_bounded(mbar, (uint32_t)((KT-1) & 1));  // last commit
    TC_FENCE_AFTER();

    // epilogue: 8 warps; warp w -> subpartition rows (w&3)*32, column half (w>>2)
    {
        int rowg = m0 + (wid & 3)*32 + lid;
        int ch2  = wid >> 2;
        for (int ch = 0; ch < 4; ch++) {
            uint32_t r[32];
            TC_LD_X32(r, tmem + ch2*128 + ch*32);
            TC_WAIT_LD();
            int col0 = n0 + ch2*128 + ch*32;
            if (mode == 1) {
                uint32_t packed[16];
                const float* b1e = b1 + e0*nH + col0;
                #pragma unroll
                for (int c = 0; c < 32; c += 2) {
                    float a0 = __uint_as_float(r[c])   + b1e[c];
                    float a1 = __uint_as_float(r[c+1]) + b1e[c+1];
                    float s0 = a0 / (1.f + __expf(-a0)) * w0s;
                    float s1 = a1 / (1.f + __expf(-a1)) * w0s;
                    __half2 h2 = __floats2half2_rn(s0, s1);
                    packed[c>>1] = *reinterpret_cast<uint32_t*>(&h2);
                }
                __half* dst = g_h + ((size_t)bb*nS + rowg)*(2*nH) + (size_t)kslot*nH + col0;
                uint4* d4 = reinterpret_cast<uint4*>(dst);
                #pragma unroll
                for (int q = 0; q < 4; q++)
                    d4[q] = make_uint4(packed[q*4], packed[q*4+1], packed[q*4+2], packed[q*4+3]);
            } else {
                const float* b2a = b2 + e0*nD + col0;
                const float* b2b = b2 + e1*nD + col0;
                float* dst = out + ((size_t)bb*nS + rowg)*nD + col0;
                #pragma unroll
                for (int c = 0; c < 32; c += 4) {
                    float4 v;
                    v.x = __uint_as_float(r[c])   + w0s*b2a[c]   + w1s*b2b[c];
                    v.y = __uint_as_float(r[c+1]) + w0s*b2a[c+1] + w1s*b2b[c+1];
                    v.z = __uint_as_float(r[c+2]) + w0s*b2a[c+2] + w1s*b2b[c+2];
                    v.w = __uint_as_float(r[c+3]) + w0s*b2a[c+3] + w1s*b2b[c+3];
                    reinterpret_cast<float4*>(dst)[c>>2] = v;
                }
            }
        }
        TC_FENCE_BEFORE();
    }
    __syncthreads();
    if (wid == 0) {
        TC_RELINQ();
        TC_DEALLOC(tmem, 512);
    }
#else
    // ================= mma.sync fallback (K-major B, non-trans ldmatrix) =================
    uint32_t tiles = (sbase + 1024) & ~1023u;
    int wm = wid >> 1, wn = wid & 1;

    for (int half = 0; half < 2; half++) {
        load_stage(0, tiles, STAGE_TC);
        load_stage(1, tiles, STAGE_TC);
        load_stage(2, tiles, STAGE_TC);

        float acc[2][8][4];
        #pragma unroll
        for (int mf = 0; mf < 2; mf++)
            #pragma unroll
            for (int nf = 0; nf < 8; nf++)
                #pragma unroll
                for (int q = 0; q < 4; q++) acc[mf][nf][q] = 0.f;

        for (int kt = 0; kt < KT; kt++) {
            if (kt + 2 < KT) asm volatile("cp.async.wait_group 2;" ::: "memory");
            else             asm volatile("cp.async.wait_group 0;" ::: "memory");
            __syncthreads();
            if (kt + 3 < KT) load_stage(kt + 3, tiles, STAGE_TC);

            uint32_t sA = tiles + (uint32_t)(kt & (NSTG-1)) * STAGE_TC;
            uint32_t sB = sA + 128*128;
            #pragma unroll
            for (int ks = 0; ks < 4; ks++) {
                int k0 = ks * 16;
                uint32_t a[2][4], bfr[4][4];
                #pragma unroll
                for (int mf = 0; mf < 2; mf++) {
                    int row = wm*32 + mf*16 + (lid & 15);
                    int kh  = k0 + (lid >> 4)*8;
                    LDSM4(a[mf], sA + SWZ((uint32_t)(row*128 + kh*2)));
                }
                #pragma unroll
                for (int nq = 0; nq < 4; nq++) {
                    int ntile = half*128 + wn*64 + nq*16 + ((lid >> 4) & 1)*8 + (lid & 7);
                    int koff  = k0 + ((lid >> 3) & 1)*8;
                    int j = ntile >> 6, rr = ntile & 63;
                    LDSM4(bfr[nq], sB + j*8192 + SWZ((uint32_t)(rr*128 + koff*2)));
                }
                #pragma unroll
                for (int mf = 0; mf < 2; mf++)
                    #pragma unroll
                    for (int nf = 0; nf < 8; nf++)
                        MMA16816(acc[mf][nf], a[mf], bfr[nf>>1][(nf&1)*2], bfr[nf>>1][(nf&1)*2+1]);
            }
        }

        #pragma unroll
        for (int mf = 0; mf < 2; mf++) {
            #pragma unroll
            for (int hh = 0; hh < 2; hh++) {
                int rowg = m0 + wm*32 + mf*16 + (lid >> 2) + hh*8;
                if (mode == 1) {
                    __half* drow = g_h + ((size_t)bb*nS + rowg)*(2*nH) + (size_t)kslot*nH;
                    #pragma unroll
                    for (int nf = 0; nf < 8; nf++) {
                        int col = n0 + half*128 + wn*64 + nf*8 + (lid & 3)*2;
                        float a0 = acc[mf][nf][hh*2+0] + b1[e0*nH + col];
                        float a1 = acc[mf][nf][hh*2+1] + b1[e0*nH + col + 1];
                        float s0 = a0 / (1.f + __expf(-a0)) * w0s;
                        float s1 = a1 / (1.f + __expf(-a1)) * w0s;
                        __half2 h2 = __floats2half2_rn(s0, s1);
                        *reinterpret_cast<uint32_t*>(drow + col) = *reinterpret_cast<uint32_t*>(&h2);
                    }
                } else {
                    float* drow = out + ((size_t)bb*nS + rowg)*nD;
                    #pragma unroll
                    for (int nf = 0; nf < 8; nf++) {
                        int col = n0 + half*128 + wn*64 + nf*8 + (lid & 3)*2;
                        float2 v;
                        v.x = acc[mf][nf][hh*2+0] + w0s*b2[e0*nD+col]   + w1s*b2[e1*nD+col];
                        v.y = acc[mf][nf][hh*2+1] + w0s*b2[e0*nD+col+1] + w1s*b2[e1*nD+col+1];
                        *reinterpret_cast<float2*>(drow + col) = v;
                    }
                }
            }
        }
        __syncthreads();   // before next half reuses smem
    }
#endif
}

// ---------------- launch ----------------
extern "C" void kernel_launch(void* const* d_in, const int* in_sizes, int n_in,
                              void* d_out, int out_size){
    (void)in_sizes; (void)n_in;
    const float* x   = (const float*)d_in[0];
    const float* Wg1 = (const float*)d_in[1];
    const float* bg1 = (const float*)d_in[2];
    const float* Wg2 = (const float*)d_in[3];
    const float* bg2 = (const float*)d_in[4];
    const float* W1  = (const float*)d_in[5];
    const float* b1  = (const float*)d_in[6];
    const float* W2  = (const float*)d_in[7];
    const float* b2  = (const float*)d_in[8];
    float* out = (float*)d_out;

    cudaFuncSetAttribute(k_moe_gemm, cudaFuncAttributeMaxDynamicSharedMemorySize, SMEM_GEMM);

    k_zero<<<1, 256>>>();
    k_convx<<<dim3(16, nB), 256>>>(x);
    k_gate<<<nB, 256>>>(Wg1, bg1, Wg2, bg2, out, (long)out_size);
    k_convw1<<<dim3(nH/32, nD/32, nE), 256>>>(W1);   // -> g_W1t [E][H][D]
    k_convw2<<<dim3(nD/32, nH/32, nE), 256>>>(W2);   // -> g_W2t [E][D][H]
    // GEMM1: per (b,k) pair: [2048 x 4096], K=1024 — grid x = m-tile (fastest)
    k_moe_gemm<<<dim3(nS/TMM, nH/TNN, nB*2), 256, SMEM_GEMM>>>(b1, b2, out, 1);
    // GEMM2: per b: [2048 x 1024], K=8192 over concatenated experts
    k_moe_gemm<<<dim3(nS/TMM, nD/TNN, nB), 256, SMEM_GEMM>>>(b1, b2, out, 2);
}

// round 12
// speedup vs baseline: 1.0959x; 1.0959x over previous
#include <cuda_runtime.h>
#include <cuda_fp16.h>
#include <cstdint>
#include <cstddef>

// ---------------- problem dims ----------------
#define nB 8
#define nS 2048
#define nD 1024
#define nH 4096
#define nE 8
constexpr int TMM = 128, TNN = 256;               // per-CTA M, pair N
constexpr int NSTG = 4;                           // pipeline stages
constexpr int STAGE_CG2 = 16384 + 16384;          // A 16KB + B-half 16KB
constexpr int STAGE_FB  = 16384 + 32768;          // fallback: A + full B
constexpr int SMEM_GEMM = 1024 + NSTG*STAGE_FB;   // 197632 (covers both paths)

#define SWZ(o) ((o) ^ (((o) >> 3) & 0x70u))

// Arch-specific gate: tcgen05 exists only in sm_103a/sm_100a cubins.
#if defined(__CUDA_ARCH__) && (defined(__CUDA_ARCH_FEAT_SM103_ALL) || \
    defined(__CUDA_ARCH_FEAT_SM100_ALL) || \
    (defined(__CUDA_ARCH_SPECIFIC__) && (__CUDA_ARCH_SPECIFIC__ >= 1000)))
#define HAS_TCGEN05 1
#else
#define HAS_TCGEN05 0
#endif

// idesc kind::f16 cg2 (mirrors test_2cta_mma_bf16, fp16 => atype/btype=0):
// F32 accum (bit4), N=64 -> (N/8)<<17, M_TOTAL=256 -> (256/16)<<24.
constexpr uint32_t IDESC2 = (1u<<4) | ((64u/8)<<17) | ((256u/16)<<24);
// K-major SW128 smem descriptor: LBO=1, SBO=64
static __device__ constexpr uint64_t DESC_K  =
    (uint64_t(2)<<61) | (uint64_t(1)<<46) | (uint64_t(64)<<32) | (uint64_t(1)<<16);

// ---------------- device scratch ----------------
__device__ __align__(256) __half g_xh [nB*nS*nD];
__device__ __align__(256) __half g_W1t[(size_t)nE*nH*nD];   // W1^T: [E][H][D]
__device__ __align__(256) __half g_W2t[(size_t)nE*nD*nH];   // W2^T: [E][D][H]
__device__ __align__(256) __half g_h  [(size_t)nB*nS*2*nH];
__device__ float g_rout[nB*nD];
__device__ float g_tw  [nB*2];
__device__ int   g_tidx[nB*2];
__device__ int   g_used[nE];

// ---------------- portable PTX helpers ----------------
__device__ __forceinline__ uint32_t smem_u32(const void* p){
    uint32_t a;
    asm("{ .reg .u64 t; cvta.to.shared.u64 t, %1; cvt.u32.u64 %0, t; }" : "=r"(a) : "l"(p));
    return a;
}
__device__ __forceinline__ void cp_async16(uint32_t s, const void* g){
    asm volatile("cp.async.cg.shared.global [%0], [%1], 16;" :: "r"(s), "l"(g));
}
__device__ __forceinline__ void cp_commit(){ asm volatile("cp.async.commit_group;" ::: "memory"); }

#define LDSM4(r, a) \
    asm volatile("ldmatrix.sync.aligned.m8n8.x4.shared.b16 {%0,%1,%2,%3}, [%4];" \
        : "=r"((r)[0]), "=r"((r)[1]), "=r"((r)[2]), "=r"((r)[3]) : "r"(a))
#define MMA16816(d, a, b0, b1) \
    asm volatile("mma.sync.aligned.m16n8k16.row.col.f32.f16.f16.f32 " \
        "{%0,%1,%2,%3}, {%4,%5,%6,%7}, {%8,%9}, {%0,%1,%2,%3};" \
        : "+f"((d)[0]), "+f"((d)[1]), "+f"((d)[2]), "+f"((d)[3]) \
        : "r"((a)[0]), "r"((a)[1]), "r"((a)[2]), "r"((a)[3]), "r"(b0), "r"(b1))

#if HAS_TCGEN05
__device__ __forceinline__ uint32_t elect_one(){
    uint32_t p;
    asm volatile("{ .reg .pred p; elect.sync _|p, 0xFFFFFFFF; selp.b32 %0, 1, 0, p; }" : "=r"(p));
    return p;
}
#define MBAR_INIT(a, c) \
    asm volatile("mbarrier.init.shared.b64 [%0], %1;" :: "r"(a), "r"(c) : "memory")
#define MBAR_ARRIVE_LOCAL(a) \
    asm volatile("mbarrier.arrive.shared.b64 _, [%0];" :: "r"(a) : "memory")
// arrive on rank-0 CTA's mbarrier at the same smem offset (works from both ranks)
#define MBAR_ARRIVE_RANK0(a) \
    asm volatile("{\n\t.reg .b32 ra;\n\t" \
        "mapa.shared::cluster.u32 ra, %0, 0;\n\t" \
        "mbarrier.arrive.shared::cluster.b64 _, [ra];\n\t}" \
        :: "r"(a) : "memory")

// Bounded parity waits: broken pipeline -> FAST wrong answer, not a timeout.
__device__ __forceinline__ bool mbar_wait_bounded(uint32_t m, uint32_t par){
    for (int i = 0; i < (1 << 17); i++){
        uint32_t d;
        asm volatile("{\n\t.reg .pred p;\n\t"
            "mbarrier.try_wait.parity.acquire.cta.shared::cta.b64 p, [%1], %2;\n\t"
            "selp.b32 %0, 1, 0, p;\n\t}" : "=r"(d) : "r"(m), "r"(par) : "memory");
        if (d) return true;
    }
    return false;
}
__device__ __forceinline__ bool mbar_wait_bounded_cl(uint32_t m, uint32_t par){
    for (int i = 0; i < (1 << 17); i++){
        uint32_t d;
        asm volatile("{\n\t.reg .pred p;\n\t"
            "mbarrier.try_wait.parity.acquire.cluster.shared::cta.b64 p, [%1], %2;\n\t"
            "selp.b32 %0, 1, 0, p;\n\t}" : "=r"(d) : "r"(m), "r"(par) : "memory");
        if (d) return true;
    }
    return false;
}

#define TC_ALLOC_CG2(sa, n) \
    asm volatile("tcgen05.alloc.cta_group::2.sync.aligned.shared::cta.b32 [%0], %1;" \
        :: "r"(sa), "r"(n) : "memory")
#define TC_DEALLOC_CG2(t, n) \
    asm volatile("tcgen05.dealloc.cta_group::2.sync.aligned.b32 %0, %1;" :: "r"(t), "r"(n))
#define TC_RELINQ_CG2() \
    asm volatile("tcgen05.relinquish_alloc_permit.cta_group::2.sync.aligned;")
#define TC_COMMIT_MC2(a) \
    asm volatile("tcgen05.commit.cta_group::2.mbarrier::arrive::one.shared::cluster.multicast::cluster.b64 [%0], %1;" \
        :: "r"(a), "h"((uint16_t)3) : "memory")
#define TC_WAIT_LD()  asm volatile("tcgen05.wait::ld.sync.aligned;" ::: "memory")
#define TC_FENCE_BEFORE() asm volatile("tcgen05.fence::before_thread_sync;" ::: "memory")
#define TC_FENCE_AFTER()  asm volatile("tcgen05.fence::after_thread_sync;" ::: "memory")
#define CLUSTER_SYNC() do { \
    asm volatile("barrier.cluster.arrive.aligned;" ::: "memory"); \
    asm volatile("barrier.cluster.wait.aligned;" ::: "memory"); \
} while(0)
#define TC_LD_X32(r, ta) \
    asm volatile( \
        "tcgen05.ld.sync.aligned.32x32b.x32.b32 " \
        "{%0, %1, %2, %3, %4, %5, %6, %7, " \
        " %8, %9, %10, %11, %12, %13, %14, %15, " \
        " %16, %17, %18, %19, %20, %21, %22, %23, " \
        " %24, %25, %26, %27, %28, %29, %30, %31}, [%32];" \
        : "=r"((r)[0]),  "=r"((r)[1]),  "=r"((r)[2]),  "=r"((r)[3]), \
          "=r"((r)[4]),  "=r"((r)[5]),  "=r"((r)[6]),  "=r"((r)[7]), \
          "=r"((r)[8]),  "=r"((r)[9]),  "=r"((r)[10]), "=r"((r)[11]), \
          "=r"((r)[12]), "=r"((r)[13]), "=r"((r)[14]), "=r"((r)[15]), \
          "=r"((r)[16]), "=r"((r)[17]), "=r"((r)[18]), "=r"((r)[19]), \
          "=r"((r)[20]), "=r"((r)[21]), "=r"((r)[22]), "=r"((r)[23]), \
          "=r"((r)[24]), "=r"((r)[25]), "=r"((r)[26]), "=r"((r)[27]), \
          "=r"((r)[28]), "=r"((r)[29]), "=r"((r)[30]), "=r"((r)[31]) \
        : "r"(ta))
__device__ __forceinline__ void mma_f16_ss_cg2(uint32_t d, uint64_t ad, uint64_t bd,
                                               uint32_t idesc, uint32_t en){
    asm volatile(
        "{\n\t.reg .pred p;\n\tsetp.ne.u32 p, %5, 0;\n\t"
        "tcgen05.mma.cta_group::2.kind::f16 [%0], %1, %2, %3, "
        "{%4,%4,%4,%4,%4,%4,%4,%4}, p;\n\t}"
        :: "r"(d), "l"(ad), "l"(bd), "r"(idesc), "r"(0u), "r"(en) : "memory");
}
#endif

// ---------------- small kernels ----------------
__global__ void k_zero(){
    int t = threadIdx.x;
    for (int i = t; i < nB*nD; i += 256) g_rout[i] = 0.f;
    if (t < nE) g_used[t] = 0;
}

__global__ void k_convx(const float* __restrict__ x){
    int sc = blockIdx.x, b = blockIdx.y, t = threadIdx.x;
    size_t base = ((size_t)b*nS + (size_t)sc*128) * nD;
    float a0=0.f, a1=0.f, a2=0.f, a3=0.f;
    for (int s = 0; s < 128; s++) {
        float4 v = reinterpret_cast<const float4*>(x + base + (size_t)s*nD)[t];
        a0 += v.x; a1 += v.y; a2 += v.z; a3 += v.w;
        __half2 ha = __floats2half2_rn(v.x, v.y);
        __half2 hb = __floats2half2_rn(v.z, v.w);
        uint2 u = make_uint2(*reinterpret_cast<uint32_t*>(&ha),
                             *reinterpret_cast<uint32_t*>(&hb));
        *reinterpret_cast<uint2*>(&g_xh[base + (size_t)s*nD + t*4]) = u;
    }
    const float inv = 1.f / (float)nS;
    atomicAdd(&g_rout[b*nD + t*4 + 0], a0*inv);
    atomicAdd(&g_rout[b*nD + t*4 + 1], a1*inv);
    atomicAdd(&g_rout[b*nD + t*4 + 2], a2*inv);
    atomicAdd(&g_rout[b*nD + t*4 + 3], a3*inv);
}

__global__ void k_gate(const float* __restrict__ Wg1, const float* __restrict__ bg1,
                       const float* __restrict__ Wg2, const float* __restrict__ bg2,
                       float* __restrict__ out, long out_size){
    __shared__ float rs[nD], gs[nD], lg[nE];
    int b = blockIdx.x, t = threadIdx.x;
    for (int i = t; i < nD; i += 256) rs[i] = g_rout[b*nD + i];
    __syncthreads();
    for (int j = t; j < nD; j += 256) {
        float a = 0.f;
        for (int d = 0; d < nD; d++) a += rs[d] * Wg1[(size_t)d*nD + j];
        a += bg1[j];
        gs[j] = a / (1.f + __expf(-a));
    }
    __syncthreads();
    if (t < nE) {
        float a = 0.f;
        for (int d = 0; d < nD; d++) a += gs[d] * Wg2[d*nE + t];
        lg[t] = a + bg2[t];
    }
    __syncthreads();
    if (t == 0) {
        int i0 = 0;
        for (int e = 1; e < nE; e++) if (lg[e] > lg[i0]) i0 = e;
        int i1 = -1;
        for (int e = 0; e < nE; e++) { if (e == i0) continue; if (i1 < 0 || lg[e] > lg[i1]) i1 = e; }
        float ex = __expf(lg[i1] - lg[i0]);
        float w0 = 1.f / (1.f + ex), w1 = ex / (1.f + ex);
        g_tw[b*2] = w0;  g_tw[b*2+1] = w1;
        g_tidx[b*2] = i0; g_tidx[b*2+1] = i1;
        g_used[i0] = 1;   g_used[i1] = 1;
        const long BSD = (long)nB*nS*nD;
        if (out_size >= BSD + 32) {
            out[BSD + b*2 + 0] = w0;  out[BSD + b*2 + 1] = w1;
            out[BSD + 16 + b*2 + 0] = (float)i0;
            out[BSD + 16 + b*2 + 1] = (float)i1;
        }
    }
}

// Transpose-convert W1 [E][D][H] fp32 -> g_W1t [E][H][D] fp16.
__global__ void k_convw1(const float* __restrict__ W){
    int e = blockIdx.z;
    if (!g_used[e]) return;
    __shared__ float s[32][33];
    int h0 = blockIdx.x * 32, d0 = blockIdx.y * 32;
    int tx = threadIdx.x & 31, ty = threadIdx.x >> 5;
    const float* Wp = W + (size_t)e*nD*nH;
    #pragma unroll
    for (int i = 0; i < 4; i++)
        s[ty + i*8][tx] = Wp[(size_t)(d0 + ty + i*8)*nH + h0 + tx];
    __syncthreads();
    __half* Wt = g_W1t + (size_t)e*nH*nD;
    #pragma unroll
    for (int i = 0; i < 4; i++)
        Wt[(size_t)(h0 + ty + i*8)*nD + d0 + tx] = __float2half_rn(s[tx][ty + i*8]);
}
// Transpose-convert W2 [E][H][D] fp32 -> g_W2t [E][D][H] fp16.
__global__ void k_convw2(const float* __restrict__ W){
    int e = blockIdx.z;
    if (!g_used[e]) return;
    __shared__ float s[32][33];
    int d0 = blockIdx.x * 32, h0 = blockIdx.y * 32;
    int tx = threadIdx.x & 31, ty = threadIdx.x >> 5;
    const float* Wp = W + (size_t)e*nH*nD;
    #pragma unroll
    for (int i = 0; i < 4; i++)
        s[ty + i*8][tx] = Wp[(size_t)(h0 + ty + i*8)*nD + d0 + tx];
    __syncthreads();
    __half* Wt = g_W2t + (size_t)e*nD*nH;
    #pragma unroll
    for (int i = 0; i < 4; i++)
        Wt[(size_t)(d0 + ty + i*8)*nH + h0 + tx] = __float2half_rn(s[tx][ty + i*8]);
}

// ---------------- fused GEMM, cg2 pair tile 256x256 (128 M-rows per CTA) ----------------
// Cluster (2,1,1) over x; pair = adjacent m-tiles; B split: for N=64 MMA j,
// CTA rank r holds B n-rows [n0 + 64j + 32r, +32) — HW reads both CTAs' halves.
__global__ __launch_bounds__(256, 1) __cluster_dims__(2, 1, 1)
void k_moe_gemm(const float* __restrict__ b1, const float* __restrict__ b2,
                float* __restrict__ out, int mode){
    extern __shared__ char smem[];
    uint32_t sbase = smem_u32(smem);
    int t = threadIdx.x, wid = t >> 5, lid = t & 31;
    int rank = blockIdx.x & 1;

    int m0 = blockIdx.x * TMM;          // per-CTA 128 rows (pair covers 256)
    int n0 = blockIdx.y * TNN;
    int z  = blockIdx.z;

    const __half* Ap; const __half *B0, *B1;
    int ldA, ldB, KT, bb, kslot = 0, e0, e1 = 0;
    float w0s, w1s = 0.f;
    if (mode == 1) {
        bb = z >> 1; kslot = z & 1;
        e0 = g_tidx[bb*2 + kslot]; w0s = g_tw[bb*2 + kslot];
        Ap = g_xh + (size_t)bb*nS*nD; ldA = nD; KT = nD/64;
        B0 = g_W1t + (size_t)e0*nH*nD; B1 = B0; ldB = nD;
    } else {
        bb = z;
        e0 = g_tidx[bb*2]; e1 = g_tidx[bb*2+1];
        w0s = g_tw[bb*2];  w1s = g_tw[bb*2+1];
        Ap = g_h + (size_t)bb*nS*2*nH; ldA = 2*nH; KT = 2*nH/64;
        B0 = g_W2t + (size_t)e0*nD*nH; B1 = g_W2t + (size_t)e1*nD*nH; ldB = nH;
    }
    const char* Abase = (const char*)Ap + (size_t)m0 * (size_t)ldA * 2;
    size_t ldAb = (size_t)ldA * 2, ldBb = (size_t)ldB * 2;

#if HAS_TCGEN05
    // ================= cg2 tcgen05 path =================
    uint32_t cmt   = sbase + 8;          // commit barrier (per CTA, multicast target)
    uint32_t rdy   = sbase + 16;         // stage-ready barrier (lives in rank0's smem)
    uint32_t tiles = (sbase + 1024) & ~1023u;

    // split-B loader: A 1024 chunks + B 1024 chunks (4 subtiles x 32 rows x 8)
    auto load_stage = [&](int kt){
        uint32_t sA = tiles + (uint32_t)(kt & (NSTG-1)) * STAGE_CG2;
        uint32_t sB = sA + 16384;
        const char* Ak = Abase + (size_t)kt * 128;
        const __half* Bexp = (mode == 2 && kt >= 64) ? B1 : B0;
        int kcol0 = (mode == 2 && kt >= 64) ? (kt - 64) * 64 : kt * 64;
        const char* Bk = (const char*)Bexp + (size_t)kcol0 * 2;
        #pragma unroll
        for (int it = 0; it < 8; it++) {
            int g = t + it * 256;
            if (g < 1024) {
                int row = g >> 3, c = g & 7;
                cp_async16(sA + SWZ((uint32_t)(row*128 + c*16)),
                           Ak + (size_t)row*ldAb + c*16);
            } else {
                int gg = g - 1024;
                int j = gg >> 8, r = (gg >> 3) & 31, c = gg & 7;
                int grow = n0 + j*64 + rank*32 + r;
                cp_async16(sB + j*4096 + SWZ((uint32_t)(r*128 + c*16)),
                           Bk + (size_t)grow*ldBb + c*16);
            }
        }
        cp_commit();
    };

    if (t == 0) {
        MBAR_INIT(cmt, 1);
        if (rank == 0) MBAR_INIT(rdy, 2);
    }
    if (wid == 0) TC_ALLOC_CG2(sbase, 512);
    __syncthreads();
    uint32_t tmem;
    asm volatile("ld.shared.b32 %0, [%1];" : "=r"(tmem) : "r"(sbase));
    CLUSTER_SYNC();                      // barriers visible before multicast/mapa

    load_stage(0); load_stage(1); load_stage(2);

    bool alive = true;
    for (int kt = 0; kt < KT; kt++) {
        if (kt + 2 < KT)      asm volatile("cp.async.wait_group 2;" ::: "memory");
        else if (kt + 1 < KT) asm volatile("cp.async.wait_group 1;" ::: "memory");
        else                  asm volatile("cp.async.wait_group 0;" ::: "memory");
        __syncthreads();
        if (t == 0) {                    // publish this CTA's stage kt to the pair
            asm volatile("fence.proxy.async.shared::cta;" ::: "memory");
            MBAR_ARRIVE_RANK0(rdy);
        }
        if (rank == 0 && wid == 0) {
            if (elect_one()) {
                bool ok = mbar_wait_bounded_cl(rdy, (uint32_t)(kt & 1));  // both CTAs ready
                TC_FENCE_AFTER();
                asm volatile("fence.proxy.async.shared::cta;" ::: "memory");
                uint32_t sA = tiles + (uint32_t)(kt & (NSTG-1)) * STAGE_CG2;
                uint32_t sB = sA + 16384;
                uint64_t ad = DESC_K | ((sA >> 4) & 0x3FFF);
                if (ok) {
                    #pragma unroll
                    for (int ks = 0; ks < 4; ks++) {
                        uint32_t en = (kt > 0 || ks > 0) ? 1u : 0u;
                        #pragma unroll
                        for (int j = 0; j < 4; j++) {
                            uint64_t bd = DESC_K | (((sB + j*4096) >> 4) & 0x3FFF);
                            mma_f16_ss_cg2(tmem + 64*j, ad + ks*2, bd + ks*2, IDESC2, en);
                        }
                    }
                }
                TC_COMMIT_MC2(cmt);      // arrives on BOTH CTAs' cmt
            }
        }
        if (kt >= 1 && alive) alive = mbar_wait_bounded(cmt, (uint32_t)((kt-1) & 1));
        if (kt + 3 < KT) load_stage(kt + 3);
    }
    if (alive) alive = mbar_wait_bounded(cmt, (uint32_t)((KT-1) & 1));   // last commit
    TC_FENCE_AFTER();

    // epilogue: each CTA reads its own TMEM (its 128 m-rows x 256 cols)
    {
        int rowg = m0 + (wid & 3)*32 + lid;
        int ch2  = wid >> 2;
        for (int ch = 0; ch < 4; ch++) {
            uint32_t r[32];
            TC_LD_X32(r, tmem + ch2*128 + ch*32);
            TC_WAIT_LD();
            int col0 = n0 + ch2*128 + ch*32;
            if (mode == 1) {
                uint32_t packed[16];
                const float* b1e = b1 + e0*nH + col0;
                #pragma unroll
                for (int c = 0; c < 32; c += 2) {
                    float a0 = __uint_as_float(r[c])   + b1e[c];
                    float a1 = __uint_as_float(r[c+1]) + b1e[c+1];
                    float s0 = a0 / (1.f + __expf(-a0)) * w0s;
                    float s1 = a1 / (1.f + __expf(-a1)) * w0s;
                    __half2 h2 = __floats2half2_rn(s0, s1);
                    packed[c>>1] = *reinterpret_cast<uint32_t*>(&h2);
                }
                __half* dst = g_h + ((size_t)bb*nS + rowg)*(2*nH) + (size_t)kslot*nH + col0;
                uint4* d4 = reinterpret_cast<uint4*>(dst);
                #pragma unroll
                for (int q = 0; q < 4; q++)
                    d4[q] = make_uint4(packed[q*4], packed[q*4+1], packed[q*4+2], packed[q*4+3]);
            } else {
                const float* b2a = b2 + e0*nD + col0;
                const float* b2b = b2 + e1*nD + col0;
                float* dst = out + ((size_t)bb*nS + rowg)*nD + col0;
                #pragma unroll
                for (int c = 0; c < 32; c += 4) {
                    float4 v;
                    v.x = __uint_as_float(r[c])   + w0s*b2a[c]   + w1s*b2b[c];
                    v.y = __uint_as_float(r[c+1]) + w0s*b2a[c+1] + w1s*b2b[c+1];
                    v.z = __uint_as_float(r[c+2]) + w0s*b2a[c+2] + w1s*b2b[c+2];
                    v.w = __uint_as_float(r[c+3]) + w0s*b2a[c+3] + w1s*b2b[c+3];
                    reinterpret_cast<float4*>(dst)[c>>2] = v;
                }
            }
        }
        TC_FENCE_BEFORE();
    }
    __syncthreads();
    CLUSTER_SYNC();                      // pair done before collective dealloc
    if (wid == 0) {
        TC_RELINQ_CG2();
        TC_DEALLOC_CG2(tmem, 512);
    }
    CLUSTER_SYNC();
#else
    // ================= mma.sync fallback (full-B loader, per-CTA 128x256) =================
    uint32_t tiles = (sbase + 1024) & ~1023u;
    int wm = wid >> 1, wn = wid & 1;

    auto load_stage_fb = [&](int kt){
        uint32_t sA = tiles + (uint32_t)(kt & (NSTG-1)) * STAGE_FB;
        uint32_t sB = sA + 16384;
        const char* Ak = Abase + (size_t)kt * 128;
        const __half* Bexp = (mode == 2 && kt >= 64) ? B1 : B0;
        int kcol0 = (mode == 2 && kt >= 64) ? (kt - 64) * 64 : kt * 64;
        const char* Bk = (const char*)Bexp + (size_t)n0 * ldBb + (size_t)kcol0 * 2;
        #pragma unroll
        for (int it = 0; it < 12; it++) {
            int g = t + it * 256;
            if (g < 1024) {
                int row = g >> 3, c = g & 7;
                cp_async16(sA + SWZ((uint32_t)(row*128 + c*16)),
                           Ak + (size_t)row*ldAb + c*16);
            } else {
                int gg = g - 1024;
                int j = gg >> 9, r = (gg >> 3) & 63, c = gg & 7;
                cp_async16(sB + j*8192 + SWZ((uint32_t)(r*128 + c*16)),
                           Bk + (size_t)(j*64 + r)*ldBb + c*16);
            }
        }
        cp_commit();
    };

    for (int half = 0; half < 2; half++) {
        load_stage_fb(0); load_stage_fb(1); load_stage_fb(2);

        float acc[2][8][4];
        #pragma unroll
        for (int mf = 0; mf < 2; mf++)
            #pragma unroll
            for (int nf = 0; nf < 8; nf++)
                #pragma unroll
                for (int q = 0; q < 4; q++) acc[mf][nf][q] = 0.f;

        for (int kt = 0; kt < KT; kt++) {
            if (kt + 2 < KT) asm volatile("cp.async.wait_group 2;" ::: "memory");
            else             asm volatile("cp.async.wait_group 0;" ::: "memory");
            __syncthreads();
            if (kt + 3 < KT) load_stage_fb(kt + 3);

            uint32_t sA = tiles + (uint32_t)(kt & (NSTG-1)) * STAGE_FB;
            uint32_t sB = sA + 16384;
            #pragma unroll
            for (int ks = 0; ks < 4; ks++) {
                int k0 = ks * 16;
                uint32_t a[2][4], bfr[4][4];
                #pragma unroll
                for (int mf = 0; mf < 2; mf++) {
                    int row = wm*32 + mf*16 + (lid & 15);
                    int kh  = k0 + (lid >> 4)*8;
                    LDSM4(a[mf], sA + SWZ((uint32_t)(row*128 + kh*2)));
                }
                #pragma unroll
                for (int nq = 0; nq < 4; nq++) {
                    int ntile = half*128 + wn*64 + nq*16 + ((lid >> 4) & 1)*8 + (lid & 7);
                    int koff  = k0 + ((lid >> 3) & 1)*8;
                    int j = ntile >> 6, rr = ntile & 63;
                    LDSM4(bfr[nq], sB + j*8192 + SWZ((uint32_t)(rr*128 + koff*2)));
                }
                #pragma unroll
                for (int mf = 0; mf < 2; mf++)
                    #pragma unroll
                    for (int nf = 0; nf < 8; nf++)
                        MMA16816(acc[mf][nf], a[mf], bfr[nf>>1][(nf&1)*2], bfr[nf>>1][(nf&1)*2+1]);
            }
        }

        #pragma unroll
        for (int mf = 0; mf < 2; mf++) {
            #pragma unroll
            for (int hh = 0; hh < 2; hh++) {
                int rowg = m0 + wm*32 + mf*16 + (lid >> 2) + hh*8;
                if (mode == 1) {
                    __half* drow = g_h + ((size_t)bb*nS + rowg)*(2*nH) + (size_t)kslot*nH;
                    #pragma unroll
                    for (int nf = 0; nf < 8; nf++) {
                        int col = n0 + half*128 + wn*64 + nf*8 + (lid & 3)*2;
                        float a0 = acc[mf][nf][hh*2+0] + b1[e0*nH + col];
                        float a1 = acc[mf][nf][hh*2+1] + b1[e0*nH + col + 1];
                        float s0 = a0 / (1.f + __expf(-a0)) * w0s;
                        float s1 = a1 / (1.f + __expf(-a1)) * w0s;
                        __half2 h2 = __floats2half2_rn(s0, s1);
                        *reinterpret_cast<uint32_t*>(drow + col) = *reinterpret_cast<uint32_t*>(&h2);
                    }
                } else {
                    float* drow = out + ((size_t)bb*nS + rowg)*nD;
                    #pragma unroll
                    for (int nf = 0; nf < 8; nf++) {
                        int col = n0 + half*128 + wn*64 + nf*8 + (lid & 3)*2;
                        float2 v;
                        v.x = acc[mf][nf][hh*2+0] + w0s*b2[e0*nD+col]   + w1s*b2[e1*nD+col];
                        v.y = acc[mf][nf][hh*2+1] + w0s*b2[e0*nD+col+1] + w1s*b2[e1*nD+col+1];
                        *reinterpret_cast<float2*>(drow + col) = v;
                    }
                }
            }
        }
        __syncthreads();
    }
#endif
}

// ---------------- launch ----------------
extern "C" void kernel_launch(void* const* d_in, const int* in_sizes, int n_in,
                              void* d_out, int out_size){
    (void)in_sizes; (void)n_in;
    const float* x   = (const float*)d_in[0];
    const float* Wg1 = (const float*)d_in[1];
    const float* bg1 = (const float*)d_in[2];
    const float* Wg2 = (const float*)d_in[3];
    const float* bg2 = (const float*)d_in[4];
    const float* W1  = (const float*)d_in[5];
    const float* b1  = (const float*)d_in[6];
    const float* W2  = (const float*)d_in[7];
    const float* b2  = (const float*)d_in[8];
    float* out = (float*)d_out;

    cudaFuncSetAttribute(k_moe_gemm, cudaFuncAttributeMaxDynamicSharedMemorySize, SMEM_GEMM);

    k_zero<<<1, 256>>>();
    k_convx<<<dim3(16, nB), 256>>>(x);
    k_gate<<<nB, 256>>>(Wg1, bg1, Wg2, bg2, out, (long)out_size);
    k_convw1<<<dim3(nH/32, nD/32, nE), 256>>>(W1);   // -> g_W1t [E][H][D]
    k_convw2<<<dim3(nD/32, nH/32, nE), 256>>>(W2);   // -> g_W2t [E][D][H]
    // GEMM1: per (b,k) pair: [2048 x 4096], K=1024; x = m (cluster pairs adjacent)
    k_moe_gemm<<<dim3(nS/TMM, nH/TNN, nB*2), 256, SMEM_GEMM>>>(b1, b2, out, 1);
    // GEMM2: per b: [2048 x 1024], K=8192 over concatenated experts
    k_moe_gemm<<<dim3(nS/TMM, nD/TNN, nB), 256, SMEM_GEMM>>>(b1, b2, out, 2);
}